// round 2
// baseline (speedup 1.0000x reference)
#include <cuda_runtime.h>
#include <math.h>

#define TSEQ 384
#define DM   768
#define DI   3072
#define DS   128
#define DR   48
#define XD   304   // DT_RANK + 2*D_STATE
#define HMLP 768

// ---------------- scratch (device globals: allocation-free rule) ----------------
__device__ float g_u[3][TSEQ][DM];        // rmsnorm output (reused)
__device__ float g_xz[3][TSEQ][2*DI];     // in_proj output: x | z
__device__ float g_xc[3][TSEQ][DI];       // conv+silu output
__device__ float g_xdbl[3][TSEQ][XD];     // x_proj output: dt | B | C
__device__ float g_delta[3][TSEQ][DI];    // softplus(dt @ dtW + b)
__device__ float g_y[3][TSEQ][DI];        // scan output * silu(z)
__device__ float g_mid[3][TSEQ][DM];      // residual after mamba
__device__ float g_h[3][TSEQ][2*HMLP];    // fc1 output
__device__ float g_ag[3][TSEQ][HMLP];     // silu(g)*a

__device__ __forceinline__ float siluf(float z) { return z * (1.f / (1.f + __expf(-z))); }

// ---------------- rmsnorm ----------------
__global__ void rmsnorm_kernel(const float* __restrict__ in, size_t inSeg,
                               const float* __restrict__ w, size_t wSeg,
                               float* __restrict__ out, size_t outSeg)
{
    int seg = blockIdx.z, t = blockIdx.x;
    const float* row = in + (size_t)seg * inSeg + (size_t)t * DM;
    const float* wr  = w + (size_t)seg * wSeg;
    float* orow      = out + (size_t)seg * outSeg + (size_t)t * DM;

    float s = 0.f;
    for (int j = threadIdx.x; j < DM; j += blockDim.x) { float v = row[j]; s = fmaf(v, v, s); }
    for (int o = 16; o; o >>= 1) s += __shfl_xor_sync(~0u, s, o);

    __shared__ float red[8];
    __shared__ float rs;
    int wid = threadIdx.x >> 5, lane = threadIdx.x & 31;
    if (!lane) red[wid] = s;
    __syncthreads();
    if (threadIdx.x == 0) {
        float tot = 0.f;
        #pragma unroll
        for (int i = 0; i < 8; i++) tot += red[i];
        rs = rsqrtf(tot * (1.f / DM) + 1e-6f);
    }
    __syncthreads();
    float r = rs;
    for (int j = threadIdx.x; j < DM; j += blockDim.x) orow[j] = row[j] * r * wr[j];
}

// ---------------- generic tiled fp32 GEMM: C[m,n] = sum_k A[m,k]*W[n,k] ----------------
enum { EP_NONE = 0, EP_BIAS = 1, EP_BIAS_SOFTPLUS = 2, EP_RES = 3, EP_RES_BIAS = 4 };

__global__ __launch_bounds__(256) void gemm_kernel(
    const float* __restrict__ A, size_t aSeg, int lda,
    const float* __restrict__ W, size_t wSeg,
    float* __restrict__ C, size_t cSeg,
    const float* __restrict__ bias, size_t biasSeg,
    const float* __restrict__ res, size_t resSeg,
    int N, int K, int mode)
{
    int seg = blockIdx.z;
    A += (size_t)seg * aSeg;
    W += (size_t)seg * wSeg;
    C += (size_t)seg * cSeg;

    const int m0 = blockIdx.x * 64, n0 = blockIdx.y * 64;

    __shared__ __align__(16) float As[16 * 64];   // [k][m]
    __shared__ __align__(16) float Ws[16 * 64];   // [k][n]

    int tid  = threadIdx.x;
    int lrow = tid >> 2;          // 0..63
    int lc4  = (tid & 3) * 4;     // 0,4,8,12
    int ty   = tid >> 4;          // 0..15
    int tx   = tid & 15;          // 0..15

    float acc[4][4];
    #pragma unroll
    for (int r = 0; r < 4; r++)
        #pragma unroll
        for (int c = 0; c < 4; c++) acc[r][c] = 0.f;

    bool wok = (n0 + lrow) < N;
    const float* aptr = A + (size_t)(m0 + lrow) * lda + lc4;
    const float* wptr = W + (size_t)(n0 + lrow) * K + lc4;

    for (int k0 = 0; k0 < K; k0 += 16) {
        float4 av = *reinterpret_cast<const float4*>(aptr + k0);
        float4 wv = wok ? *reinterpret_cast<const float4*>(wptr + k0)
                        : make_float4(0.f, 0.f, 0.f, 0.f);
        As[(lc4 + 0) * 64 + lrow] = av.x;
        As[(lc4 + 1) * 64 + lrow] = av.y;
        As[(lc4 + 2) * 64 + lrow] = av.z;
        As[(lc4 + 3) * 64 + lrow] = av.w;
        Ws[(lc4 + 0) * 64 + lrow] = wv.x;
        Ws[(lc4 + 1) * 64 + lrow] = wv.y;
        Ws[(lc4 + 2) * 64 + lrow] = wv.z;
        Ws[(lc4 + 3) * 64 + lrow] = wv.w;
        __syncthreads();

        #pragma unroll
        for (int kk = 0; kk < 16; kk++) {
            float4 a = *reinterpret_cast<const float4*>(&As[kk * 64 + ty * 4]);
            float4 b = *reinterpret_cast<const float4*>(&Ws[kk * 64 + tx * 4]);
            float ar[4] = {a.x, a.y, a.z, a.w};
            float br[4] = {b.x, b.y, b.z, b.w};
            #pragma unroll
            for (int r = 0; r < 4; r++)
                #pragma unroll
                for (int c = 0; c < 4; c++)
                    acc[r][c] = fmaf(ar[r], br[c], acc[r][c]);
        }
        __syncthreads();
    }

    const float* bseg = bias ? bias + (size_t)seg * biasSeg : nullptr;
    const float* rseg = res ? res + (size_t)seg * resSeg : nullptr;

    #pragma unroll
    for (int r = 0; r < 4; r++) {
        int m = m0 + ty * 4 + r;
        #pragma unroll
        for (int c = 0; c < 4; c++) {
            int n = n0 + tx * 4 + c;
            if (n < N) {
                float v = acc[r][c];
                if (mode == EP_BIAS || mode == EP_BIAS_SOFTPLUS || mode == EP_RES_BIAS)
                    v += bseg[n];
                if (mode == EP_BIAS_SOFTPLUS)
                    v = (v > 20.f) ? v : log1pf(expf(v));
                if (mode == EP_RES || mode == EP_RES_BIAS)
                    v += rseg[(size_t)m * N + n];
                C[(size_t)m * N + n] = v;
            }
        }
    }
}

// ---------------- depthwise causal conv (width 4) + silu ----------------
__global__ void conv_silu_kernel(const float* __restrict__ cw, const float* __restrict__ cb)
{
    int seg = blockIdx.z;
    int idx = blockIdx.x * blockDim.x + threadIdx.x;   // t*DI + d
    int t = idx / DI, d = idx - t * DI;
    const float* w = cw + ((size_t)seg * DI + d) * 4;
    float acc = cb[(size_t)seg * DI + d];
    #pragma unroll
    for (int k = 0; k < 4; k++) {
        int tt = t - 3 + k;
        if (tt >= 0) acc = fmaf(g_xz[seg][tt][d], w[k], acc);
    }
    g_xc[seg][t][d] = siluf(acc);
}

// ---------------- selective scan: 1 warp per channel, 4 states per lane ----------------
__global__ __launch_bounds__(256) void scan_kernel(const float* __restrict__ A_log,
                                                   const float* __restrict__ D_skip)
{
    int seg  = blockIdx.z;
    int warp = threadIdx.x >> 5;
    int lane = threadIdx.x & 31;
    int d    = blockIdx.x * 8 + warp;   // 0..3071

    const float* Alog = A_log + ((size_t)seg * DI + d) * DS;
    float a[4], h[4];
    #pragma unroll
    for (int j = 0; j < 4; j++) {
        a[j] = -expf(Alog[lane + 32 * j]);
        h[j] = 0.f;
    }
    float Dsk = D_skip[(size_t)seg * DI + d];

    const float* dptr = &g_delta[seg][0][d];
    const float* xptr = &g_xc[seg][0][d];
    const float* zptr = &g_xz[seg][0][DI + d];   // row stride of g_xz is 2*DI!
    float*       yptr = &g_y[seg][0][d];
    const float* bc   = &g_xdbl[seg][0][0];

    for (int t = 0; t < TSEQ; t++) {
        float dt = dptr[(size_t)t * DI];
        float xt = xptr[(size_t)t * DI];
        float dx = dt * xt;
        const float* row = bc + (size_t)t * XD;
        float y = 0.f;
        #pragma unroll
        for (int j = 0; j < 4; j++) {
            float e  = __expf(dt * a[j]);
            float Bn = row[DR + lane + 32 * j];
            float Cn = row[DR + DS + lane + 32 * j];
            h[j] = fmaf(e, h[j], dx * Bn);
            y    = fmaf(h[j], Cn, y);
        }
        #pragma unroll
        for (int o = 16; o; o >>= 1) y += __shfl_xor_sync(~0u, y, o);
        if (!lane) {
            float z = zptr[(size_t)t * 2 * DI];   // FIX: stride 2*DI, not DI
            yptr[(size_t)t * DI] = fmaf(xt, Dsk, y) * siluf(z);
        }
    }
}

// ---------------- gMLP gate: silu(g)*a ----------------
__global__ void gate_kernel()
{
    int seg = blockIdx.z;
    int idx = blockIdx.x * blockDim.x + threadIdx.x;  // t*HMLP + j
    int t = idx / HMLP, j = idx - t * HMLP;
    float av = g_h[seg][t][j];
    float gv = g_h[seg][t][HMLP + j];
    g_ag[seg][t][j] = siluf(gv) * av;
}

// ---------------- host ----------------
static float* symaddr(const void* sym)
{
    void* p = nullptr;
    cudaGetSymbolAddress(&p, sym);
    return (float*)p;
}

extern "C" void kernel_launch(void* const* d_in, const int* in_sizes, int n_in,
                              void* d_out, int out_size)
{
    const float* x         = (const float*)d_in[0];
    const float* ln_w      = (const float*)d_in[1];
    const float* in_proj_w = (const float*)d_in[2];
    const float* conv_w    = (const float*)d_in[3];
    const float* conv_b    = (const float*)d_in[4];
    const float* x_proj_w  = (const float*)d_in[5];
    const float* dt_proj_w = (const float*)d_in[6];
    const float* dt_proj_b = (const float*)d_in[7];
    const float* A_log     = (const float*)d_in[8];
    const float* D_skip    = (const float*)d_in[9];
    const float* out_proj_w= (const float*)d_in[10];
    const float* fc1_w     = (const float*)d_in[11];
    const float* fc1_b     = (const float*)d_in[12];
    const float* fc2_w     = (const float*)d_in[13];
    const float* fc2_b     = (const float*)d_in[14];
    float* out = (float*)d_out;

    float* pu    = symaddr(g_u);
    float* pxz   = symaddr(g_xz);
    float* pxc   = symaddr(g_xc);
    float* pxdbl = symaddr(g_xdbl);
    float* pdel  = symaddr(g_delta);
    float* py    = symaddr(g_y);
    float* pmid  = symaddr(g_mid);
    float* ph    = symaddr(g_h);
    float* pag   = symaddr(g_ag);

    const size_t T768 = (size_t)TSEQ * DM;

    // 1. rmsnorm(x, ln_w[2*seg]) -> u
    rmsnorm_kernel<<<dim3(TSEQ, 1, 3), 256>>>(x, T768, ln_w, 2 * (size_t)DM, pu, T768);

    // 2. in_proj: u @ W^T -> xz (384 x 6144)
    gemm_kernel<<<dim3(6, 96, 3), 256>>>(pu, T768, DM,
        in_proj_w, (size_t)2 * DI * DM,
        pxz, (size_t)TSEQ * 2 * DI,
        nullptr, 0, nullptr, 0, 2 * DI, DM, EP_NONE);

    // 3. causal depthwise conv + silu
    conv_silu_kernel<<<dim3(TSEQ * DI / 256, 1, 3), 256>>>(conv_w, conv_b);

    // 4. x_proj: xc @ W^T -> x_dbl (384 x 304)
    gemm_kernel<<<dim3(6, 5, 3), 256>>>(pxc, (size_t)TSEQ * DI, DI,
        x_proj_w, (size_t)XD * DI,
        pxdbl, (size_t)TSEQ * XD,
        nullptr, 0, nullptr, 0, XD, DI, EP_NONE);

    // 5. delta = softplus(dt @ dtW^T + b)  (A = x_dbl[:, :48], lda=304)
    gemm_kernel<<<dim3(6, 48, 3), 256>>>(pxdbl, (size_t)TSEQ * XD, XD,
        dt_proj_w, (size_t)DI * DR,
        pdel, (size_t)TSEQ * DI,
        dt_proj_b, DI, nullptr, 0, DI, DR, EP_BIAS_SOFTPLUS);

    // 6. selective scan + D skip + silu(z) gate -> y
    scan_kernel<<<dim3(DI / 8, 1, 3), 256>>>(A_log, D_skip);

    // 7. out_proj + residual(x) -> mid
    gemm_kernel<<<dim3(6, 12, 3), 256>>>(py, (size_t)TSEQ * DI, DI,
        out_proj_w, (size_t)DM * DI,
        pmid, T768,
        nullptr, 0, x, T768, DM, DI, EP_RES);

    // 8. rmsnorm(mid, ln_w[2*seg+1]) -> u
    rmsnorm_kernel<<<dim3(TSEQ, 1, 3), 256>>>(pmid, T768, ln_w + DM, 2 * (size_t)DM, pu, T768);

    // 9. fc1 + bias -> h (384 x 1536)
    gemm_kernel<<<dim3(6, 24, 3), 256>>>(pu, T768, DM,
        fc1_w, (size_t)2 * HMLP * DM,
        ph, (size_t)TSEQ * 2 * HMLP,
        fc1_b, 2 * HMLP, nullptr, 0, 2 * HMLP, DM, EP_BIAS);

    // 10. gate: silu(g)*a
    gate_kernel<<<dim3(TSEQ * HMLP / 256, 1, 3), 256>>>();

    // 11. fc2 + bias + residual(mid) -> out
    gemm_kernel<<<dim3(6, 12, 3), 256>>>(pag, (size_t)TSEQ * HMLP, HMLP,
        fc2_w, (size_t)DM * HMLP,
        out, T768,
        fc2_b, DM, pmid, T768, DM, HMLP, EP_RES_BIAS);
}